// round 3
// baseline (speedup 1.0000x reference)
#include <cuda_runtime.h>

#define AN 49104
#define BB 8
#define MM 50
#define CC 90
#define TPB 256

// Per-batch accumulators (device globals: no allocation allowed)
__device__ double g_cls[BB];
__device__ double g_reg[BB];
__device__ int    g_np[BB];

__global__ void initK() {
    int t = threadIdx.x;
    if (t < BB) { g_cls[t] = 0.0; g_reg[t] = 0.0; g_np[t] = 0; }
}

__device__ __forceinline__ float warpSumF(float v) {
#pragma unroll
    for (int o = 16; o; o >>= 1) v += __shfl_down_sync(0xffffffffu, v, o);
    return v;
}
__device__ __forceinline__ int warpSumI(int v) {
#pragma unroll
    for (int o = 16; o; o >>= 1) v += __shfl_down_sync(0xffffffffu, v, o);
    return v;
}

__global__ __launch_bounds__(TPB) void focalK(
    const float* __restrict__ boxes,    // [B, M, 4] (x1,y1,x2,y2)
    const int*   __restrict__ labels,   // [B, M]
    const float* __restrict__ regr,     // [B, A, 4]
    const float* __restrict__ cls,      // [B, A, C]
    const float* __restrict__ anchors)  // [1, A, 4] (y1,x1,y2,x2)
{
    __shared__ float sx1[MM], sy1[MM], sx2[MM], sy2[MM], sar[MM];
    __shared__ int   slab[MM];
    __shared__ float sred[TPB / 32];
    __shared__ int   sredi[TPB / 32];

    const int b   = blockIdx.y;
    const int a0  = blockIdx.x * TPB;
    const int tid = threadIdx.x;
    const int a   = a0 + tid;

    // Load this batch's GT boxes into smem
    if (tid < MM) {
        float4 v = ((const float4*)boxes)[b * MM + tid];
        sx1[tid] = v.x; sy1[tid] = v.y; sx2[tid] = v.z; sy2[tid] = v.w;
        sar[tid] = (v.z - v.x) * (v.w - v.y);
        slab[tid] = labels[b * MM + tid];
    }
    __syncthreads();

    // ---------------- Phase 1: anchor assignment + regression loss ----------
    int   ispos  = 0;
    int   mylab  = -1;
    float regsum = 0.0f;

    if (a < AN) {
        float4 av = ((const float4*)anchors)[a];
        float ay1 = av.x, ax1 = av.y, ay2 = av.z, ax2 = av.w;
        float aw = ax2 - ax1, ah = ay2 - ay1;
        float acx = ax1 + 0.5f * aw, acy = ay1 + 0.5f * ah;
        float aar = ah * aw;

        float best = -1.0f;  // matches ref: invalid boxes scored -1.0
        int   bj   = 0;      // argmax = first occurrence of max -> strict '>'
#pragma unroll 5
        for (int j = 0; j < MM; j++) {
            if (slab[j] != 0) {   // uniform across warp
                float iw = fminf(ax2, sx2[j]) - fmaxf(ax1, sx1[j]);
                float ih = fminf(ay2, sy2[j]) - fmaxf(ay1, sy1[j]);
                iw = fmaxf(iw, 0.0f);
                ih = fmaxf(ih, 0.0f);
                float inter = iw * ih;
                float ua = fmaxf(aar + sar[j] - inter, 1e-8f);
                float iou = __fdividef(inter, ua);
                if (iou > best) { best = iou; bj = j; }
            }
        }

        float gx1 = sx1[bj], gy1 = sy1[bj], gx2 = sx2[bj], gy2 = sy2[bj];
        bool big = (gx2 - gx1) * (gy2 - gy1) > 100.0f;
        bool pos = big ? (best >= 0.5f) : (best >= 0.15f);

        if (pos) {
            ispos = 1;
            mylab = slab[bj] - 1;
            float gw0 = gx2 - gx1, gh0 = gy2 - gy1;
            float gcx = gx1 + 0.5f * gw0, gcy = gy1 + 0.5f * gh0;
            float gw = fmaxf(gw0, 1.0f), gh = fmaxf(gh0, 1.0f);
            float tdy = __fdividef(gcy - acy, ah);
            float tdx = __fdividef(gcx - acx, aw);
            float tdh = __logf(__fdividef(gh, ah));
            float tdw = __logf(__fdividef(gw, aw));
            float4 rv = ((const float4*)regr)[(size_t)b * AN + a];
            float d0 = fabsf(tdy - rv.x);
            float d1 = fabsf(tdx - rv.y);
            float d2 = fabsf(tdh - rv.z);
            float d3 = fabsf(tdw - rv.w);
            const float th = 1.0f / 9.0f;
            const float c5 = 0.5f / 9.0f;
            regsum  = (d0 <= th) ? 4.5f * d0 * d0 : d0 - c5;
            regsum += (d1 <= th) ? 4.5f * d1 * d1 : d1 - c5;
            regsum += (d2 <= th) ? 4.5f * d2 * d2 : d2 - c5;
            regsum += (d3 <= th) ? 4.5f * d3 * d3 : d3 - c5;
        }
    }

    // Block reduce (reg_sum, num_pos) -> one atomic each per block
    {
        float rs = warpSumF(regsum);
        int   ni = warpSumI(ispos);
        int wid = tid >> 5, lid = tid & 31;
        if (lid == 0) { sred[wid] = rs; sredi[wid] = ni; }
        __syncthreads();
        if (wid == 0) {
            float r2 = (lid < TPB / 32) ? sred[lid] : 0.0f;
            int   n2 = (lid < TPB / 32) ? sredi[lid] : 0;
            r2 = warpSumF(r2);
            n2 = warpSumI(n2);
            if (lid == 0) {
                if (n2 > 0) atomicAdd(&g_np[b], n2);
                if (r2 != 0.0f) atomicAdd(&g_reg[b], (double)r2);
            }
        }
    }

    // ---------------- Phase 2: classification focal loss --------------------
    // Sum f0(c) = -0.75*c^2*log(1-c) over the whole contiguous block region
    // (pure stream, no per-element target logic), then correct the single
    // t==1 element per positive anchor with f1(c)-f0(c).
    const int nrows = min(TPB, AN - a0);
    const float* p  = cls + ((size_t)b * AN + a0) * (size_t)CC;
    const int n  = nrows * CC;
    const int n4 = n >> 2;
    const float4* p4 = (const float4*)p;

    float csum = 0.0f;  // accumulates c^2 * log(1-c)  (negative)
#pragma unroll 4
    for (int i = tid; i < n4; i += TPB) {
        float4 v = p4[i];
        float c0 = fminf(fmaxf(v.x, 1e-4f), 1.0f - 1e-4f);
        float c1 = fminf(fmaxf(v.y, 1e-4f), 1.0f - 1e-4f);
        float c2 = fminf(fmaxf(v.z, 1e-4f), 1.0f - 1e-4f);
        float c3 = fminf(fmaxf(v.w, 1e-4f), 1.0f - 1e-4f);
        csum += c0 * c0 * __logf(1.0f - c0);
        csum += c1 * c1 * __logf(1.0f - c1);
        csum += c2 * c2 * __logf(1.0f - c2);
        csum += c3 * c3 * __logf(1.0f - c3);
    }
    for (int i = (n4 << 2) + tid; i < n; i += TPB) {
        float c = fminf(fmaxf(p[i], 1e-4f), 1.0f - 1e-4f);
        csum += c * c * __logf(1.0f - c);
    }

    float mysum = -0.75f * csum;

    if (ispos) {
        float c = fminf(fmaxf(p[tid * CC + mylab], 1e-4f), 1.0f - 1e-4f);
        float f0 = -0.75f * c * c * __logf(1.0f - c);
        float f1 = -0.25f * (1.0f - c) * (1.0f - c) * __logf(c);
        mysum += f1 - f0;
    }

    __syncthreads();  // guard sred reuse
    {
        float rs = warpSumF(mysum);
        int wid = tid >> 5, lid = tid & 31;
        if (lid == 0) sred[wid] = rs;
        __syncthreads();
        if (wid == 0) {
            float r2 = (lid < TPB / 32) ? sred[lid] : 0.0f;
            r2 = warpSumF(r2);
            if (lid == 0) atomicAdd(&g_cls[b], (double)r2);
        }
    }
}

__global__ void finalK(float* __restrict__ out) {
    if (threadIdx.x == 0 && blockIdx.x == 0) {
        double clsm = 0.0, regm = 0.0;
        for (int b = 0; b < BB; b++) {
            double np = (double)g_np[b];
            double npc = np > 1.0 ? np : 1.0;
            clsm += g_cls[b] / npc;
            if (g_np[b] > 0) regm += g_reg[b] / (np * 4.0);
        }
        out[0] = (float)(clsm / (double)BB);
        out[1] = (float)(regm / (double)BB * 50.0);
    }
}

extern "C" void kernel_launch(void* const* d_in, const int* in_sizes, int n_in,
                              void* d_out, int out_size) {
    const float* boxes   = nullptr;
    const int*   labels  = nullptr;
    const float* regr    = nullptr;
    const float* clsp    = nullptr;
    const float* anchors = nullptr;

    // Bind inputs by element count (all distinct, robust to ordering):
    for (int i = 0; i < n_in; i++) {
        switch (in_sizes[i]) {
            case BB * MM * 4:       boxes   = (const float*)d_in[i]; break;  // 1600
            case BB * MM:           labels  = (const int*)d_in[i];   break;  // 400
            case BB * AN * 4:       regr    = (const float*)d_in[i]; break;  // 1571328
            case BB * AN * CC:      clsp    = (const float*)d_in[i]; break;  // 35354880
            case AN * 4:            anchors = (const float*)d_in[i]; break;  // 196416
            default: break;
        }
    }

    initK<<<1, 32>>>();
    dim3 grid((AN + TPB - 1) / TPB, BB);
    focalK<<<grid, TPB>>>(boxes, labels, regr, clsp, anchors);
    finalK<<<1, 32>>>((float*)d_out);
}